// round 15
// baseline (speedup 1.0000x reference)
#include <cuda_runtime.h>
#include <cuda_bf16.h>
#include <math_constants.h>
#include <cstdint>

// Problem constants
#define B_   4
#define T_   2048
#define OBS_ 512
#define ST_  512
#define H_   8
#define E_   64
#define BH_  (B_ * H_)          // 32
#define NQK_ (H_ * E_)          // 512

#define LOG2E_F 1.4426950408889634f

// Scratch (fp32, tf32-rounded values):
//   g_q: [bh][t][e]                      (unchanged)
//   g_k: [bh][t][e_perm]  e permuted within 8-groups: c -> c<4 ? 2c : 2(c-4)+1
//   g_v: [bh][e][t_perm]  TRANSPOSED, t permuted within 8-groups (same perm)
//   g_o: [bh][t][e]
__device__ float g_q[BH_ * T_ * E_];
__device__ float g_k[BH_ * T_ * E_];
__device__ float g_v[BH_ * T_ * E_];
__device__ float g_o[BH_ * T_ * E_];

// Pre-converted bf16 hi/lo operands (packed bf16x2 words, [row][kpair])
__device__ uint32_t g_xh[16384 * 256];   // rows 0..8191 = obs, 8192..16383 = state
__device__ uint32_t g_xl[16384 * 256];
__device__ uint32_t g_wh[3 * 512 * 256]; // [z][n][kpair]
__device__ uint32_t g_wl[3 * 512 * 256];

__device__ __forceinline__ uint32_t smem_u32(const void* p) {
    uint32_t a;
    asm("{ .reg .u64 t; cvta.to.shared.u64 t, %1; cvt.u32.u64 %0, t; }" : "=r"(a) : "l"(p));
    return a;
}
__device__ __forceinline__ float to_tf32(float x) {
    float y; asm("cvt.rna.tf32.f32 %0, %1;" : "=f"(y) : "f"(x)); return y;
}
__device__ __forceinline__ float fast_ex2(float x) {
    float y; asm("ex2.approx.f32 %0, %1;" : "=f"(y) : "f"(x)); return y;
}
// m16n8k8 tf32 mma (A row-major, B col-major), D = A*B + D
__device__ __forceinline__ void mma_tf32(float* c, const uint32_t* a,
                                         uint32_t b0, uint32_t b1) {
    asm volatile(
        "mma.sync.aligned.m16n8k8.row.col.f32.tf32.tf32.f32 "
        "{%0,%1,%2,%3}, {%4,%5,%6,%7}, {%8,%9}, {%0,%1,%2,%3};"
        : "+f"(c[0]), "+f"(c[1]), "+f"(c[2]), "+f"(c[3])
        : "r"(a[0]), "r"(a[1]), "r"(a[2]), "r"(a[3]), "r"(b0), "r"(b1));
}
// m16n8k16 bf16 mma (A row-major, B col-major), D = A*B + D
__device__ __forceinline__ void mma_bf16(float* c, const uint32_t* a,
                                         uint32_t b0, uint32_t b1) {
    asm volatile(
        "mma.sync.aligned.m16n8k16.row.col.f32.bf16.bf16.f32 "
        "{%0,%1,%2,%3}, {%4,%5,%6,%7}, {%8,%9}, {%0,%1,%2,%3};"
        : "+f"(c[0]), "+f"(c[1]), "+f"(c[2]), "+f"(c[3])
        : "r"(a[0]), "r"(a[1]), "r"(a[2]), "r"(a[3]), "r"(b0), "r"(b1));
}
__device__ __forceinline__ uint32_t pack_bf16(float lo, float hi) {
    uint32_t r;
    asm("cvt.rn.bf16x2.f32 %0, %1, %2;" : "=r"(r) : "f"(hi), "f"(lo));
    return r;
}
__device__ __forceinline__ float unpk_lo(uint32_t p) { return __uint_as_float(p << 16); }
__device__ __forceinline__ float unpk_hi(uint32_t p) { return __uint_as_float(p & 0xFFFF0000u); }

__device__ __forceinline__ void cpa16(uint32_t dst, const void* src) {
    asm volatile("cp.async.cg.shared.global [%0], [%1], 16;" :: "r"(dst), "l"(src));
}
#define CP_COMMIT() asm volatile("cp.async.commit_group;" ::: "memory")
#define CP_WAIT1()  asm volatile("cp.async.wait_group 1;" ::: "memory")
#define CP_WAIT0()  asm volatile("cp.async.wait_group 0;" ::: "memory")

// perm within an 8-group: c -> c<4 ? 2c : 2(c-4)+1  (so paired (t, t+4) land adjacent)
__device__ __forceinline__ int perm8(int c) { return (c < 4) ? (2 * c) : (2 * (c - 4) + 1); }

// ---------------------------------------------------------------------------
// Kernel 0a: convert X (obs ++ state) to packed bf16 hi/lo [row][kpair]
// ---------------------------------------------------------------------------
__global__ __launch_bounds__(256) void convx_kernel(
    const float* __restrict__ obs, const float* __restrict__ st)
{
    const int idx = blockIdx.x * 256 + threadIdx.x;
    const int row = idx >> 7;
    const int c4  = (idx & 127) * 4;
    const float* src = (row < 8192) ? obs + (size_t)row * 512 + c4
                                    : st + (size_t)(row - 8192) * 512 + c4;
    const float4 x = *(const float4*)src;
    const uint32_t h0 = pack_bf16(x.x, x.y);
    const uint32_t h1 = pack_bf16(x.z, x.w);
    const uint32_t l0 = pack_bf16(x.x - unpk_lo(h0), x.y - unpk_hi(h0));
    const uint32_t l1 = pack_bf16(x.z - unpk_lo(h1), x.w - unpk_hi(h1));
    const size_t o = (size_t)row * 256 + (c4 >> 1);
    *(uint2*)&g_xh[o] = make_uint2(h0, h1);
    *(uint2*)&g_xl[o] = make_uint2(l0, l1);
}

// ---------------------------------------------------------------------------
// Kernel 0b: convert W (Wq/Wk/Wv) to transposed packed bf16 hi/lo [z][n][kpair]
// ---------------------------------------------------------------------------
__global__ __launch_bounds__(256) void convw_kernel(
    const float* __restrict__ Wq, const float* __restrict__ Wk,
    const float* __restrict__ Wv)
{
    const int z = blockIdx.z;
    const float* W = (z == 0) ? Wq : ((z == 1) ? Wk : Wv);
    const int n  = blockIdx.x * 256 + threadIdx.x;
    const int kp = blockIdx.y;
    const float x0 = W[(size_t)(2 * kp + 0) * 512 + n];
    const float x1 = W[(size_t)(2 * kp + 1) * 512 + n];
    const uint32_t h = pack_bf16(x0, x1);
    const uint32_t l = pack_bf16(x0 - unpk_lo(h), x1 - unpk_hi(h));
    const size_t o = ((size_t)z * 512 + n) * 256 + kp;
    g_wh[o] = h;
    g_wl[o] = l;
}

// ---------------------------------------------------------------------------
// Kernel 1: QKV projection, v4: 64m x 32n warp tiles; epilogue writes
// Q normal, K e-permuted, V transposed + t-permuted.
// ---------------------------------------------------------------------------
#define SA 24
#define SB 20
#define STG_A (128 * SA)
#define STG_B (128 * SB)
#define PROJ_SMEM_BYTES ((4 * STG_A + 4 * STG_B) * 4)   // 90112

__global__ __launch_bounds__(256, 2) void proj4_kernel()
{
    extern __shared__ uint32_t sm[];
    const uint32_t sb = smem_u32(sm);

    const int z = blockIdx.z;
    float* Out = (z == 0) ? g_q : ((z == 1) ? g_k : g_v);
    const float scale = (z == 0) ? 0.125f : 1.0f;
    const int row_base = (z == 0) ? 0 : 8192;

    const int m0 = blockIdx.y * 128;
    const int n0 = blockIdx.x * 128;

    const int tid  = threadIdx.x;
    const int warp = tid >> 5, lane = tid & 31;
    const int g = lane >> 2, tig = lane & 3;
    const int wm = (warp >> 2) * 64;
    const int wn = (warp & 3) * 32;

    const uint32_t* Xh = g_xh + (size_t)(row_base + m0) * 256;
    const uint32_t* Xl = g_xl + (size_t)(row_base + m0) * 256;
    const uint32_t* Wh = g_wh + ((size_t)z * 512 + n0) * 256;
    const uint32_t* Wl = g_wl + ((size_t)z * 512 + n0) * 256;

    auto load_stage = [&](int s, int k0) {
        const int kw = k0 >> 1;
        const uint32_t ah = sb + (uint32_t)(s * STG_A) * 4;
        const uint32_t al = sb + (uint32_t)((2 + s) * STG_A) * 4;
        const uint32_t bhh = sb + (uint32_t)(4 * STG_A + s * STG_B) * 4;
        const uint32_t bll = sb + (uint32_t)(4 * STG_A + (2 + s) * STG_B) * 4;
        #pragma unroll
        for (int it = 0; it < 2; it++) {
            const int u = it * 256 + tid;
            const int r = u >> 2, ch = (u & 3) * 4;
            cpa16(ah + (uint32_t)(r * SA + ch) * 4, Xh + (size_t)r * 256 + kw + ch);
            cpa16(al + (uint32_t)(r * SA + ch) * 4, Xl + (size_t)r * 256 + kw + ch);
            cpa16(bhh + (uint32_t)(r * SB + ch) * 4, Wh + (size_t)r * 256 + kw + ch);
            cpa16(bll + (uint32_t)(r * SB + ch) * 4, Wl + (size_t)r * 256 + kw + ch);
        }
    };

    float c[4][4][4];
    #pragma unroll
    for (int mf = 0; mf < 4; mf++)
        #pragma unroll
        for (int nf = 0; nf < 4; nf++)
            #pragma unroll
            for (int j = 0; j < 4; j++) c[mf][nf][j] = 0.0f;

    load_stage(0, 0);
    CP_COMMIT();

    for (int kt = 0; kt < 16; kt++) {
        if (kt < 15) {
            load_stage((kt + 1) & 1, (kt + 1) * 32);
            CP_COMMIT();
            CP_WAIT1();
        } else {
            CP_WAIT0();
        }
        __syncthreads();

        const int s = kt & 1;
        const uint32_t* Ash = sm + s * STG_A;
        const uint32_t* Asl = sm + (2 + s) * STG_A;
        const uint32_t* Bsh = sm + 4 * STG_A + s * STG_B;
        const uint32_t* Bsl = sm + 4 * STG_A + (2 + s) * STG_B;

        #pragma unroll
        for (int ks = 0; ks < 2; ks++) {
            const int kw = ks * 8 + 2 * tig;
            uint32_t ah[4][4];
            #pragma unroll
            for (int mf = 0; mf < 4; mf++) {
                const int r0 = wm + mf * 16 + g;
                const uint2 p = *(const uint2*)&Ash[r0 * SA + kw];
                const uint2 q = *(const uint2*)&Ash[(r0 + 8) * SA + kw];
                ah[mf][0] = p.x; ah[mf][1] = q.x; ah[mf][2] = p.y; ah[mf][3] = q.y;
            }
            uint2 bh[4];
            #pragma unroll
            for (int nf = 0; nf < 4; nf++) {
                const int nr = wn + nf * 8 + g;
                bh[nf] = *(const uint2*)&Bsh[nr * SB + kw];
                const uint2 bl = *(const uint2*)&Bsl[nr * SB + kw];
                #pragma unroll
                for (int mf = 0; mf < 4; mf++) {
                    mma_bf16(c[mf][nf], ah[mf], bh[nf].x, bh[nf].y);
                    mma_bf16(c[mf][nf], ah[mf], bl.x, bl.y);
                }
            }
            #pragma unroll
            for (int mf = 0; mf < 4; mf++) {
                const int r0 = wm + mf * 16 + g;
                const uint2 pl = *(const uint2*)&Asl[r0 * SA + kw];
                const uint2 ql = *(const uint2*)&Asl[(r0 + 8) * SA + kw];
                uint32_t al_[4] = { pl.x, ql.x, pl.y, ql.y };
                #pragma unroll
                for (int nf = 0; nf < 4; nf++)
                    mma_bf16(c[mf][nf], al_, bh[nf].x, bh[nf].y);
            }
        }
        __syncthreads();
    }

    // Epilogue — layout depends on z.
    const int hh = (n0 + wn) >> 6;
    const int eb = wn & 63;
    if (z == 0) {
        // Q: [bh][t][e], normal
        #pragma unroll
        for (int mf = 0; mf < 4; mf++)
            #pragma unroll
            for (int nf = 0; nf < 4; nf++) {
                const int e = eb + nf * 8 + 2 * tig;
                const int m = m0 + wm + mf * 16 + g;
                const int b = m >> 11, t = m & 2047;
                float* p0 = &Out[(((size_t)(b * H_ + hh) * T_ + t) << 6) + e];
                p0[0] = to_tf32(c[mf][nf][0] * scale);
                p0[1] = to_tf32(c[mf][nf][1] * scale);
                float* p1 = &Out[(((size_t)(b * H_ + hh) * T_ + (t + 8)) << 6) + e];
                p1[0] = to_tf32(c[mf][nf][2] * scale);
                p1[1] = to_tf32(c[mf][nf][3] * scale);
            }
    } else if (z == 1) {
        // K: [bh][t][perm(e)] — e permuted within 8-groups
        const int c0 = 2 * tig, c1 = 2 * tig + 1;
        const int p0i = perm8(c0), p1i = perm8(c1);
        #pragma unroll
        for (int mf = 0; mf < 4; mf++)
            #pragma unroll
            for (int nf = 0; nf < 4; nf++) {
                const int ebase = eb + nf * 8;
                const int m = m0 + wm + mf * 16 + g;
                const int b = m >> 11, t = m & 2047;
                float* r0 = &Out[(((size_t)(b * H_ + hh) * T_ + t) << 6) + ebase];
                r0[p0i] = to_tf32(c[mf][nf][0]);
                r0[p1i] = to_tf32(c[mf][nf][1]);
                float* r1 = &Out[(((size_t)(b * H_ + hh) * T_ + (t + 8)) << 6) + ebase];
                r1[p0i] = to_tf32(c[mf][nf][2]);
                r1[p1i] = to_tf32(c[mf][nf][3]);
            }
    } else {
        // V: [bh][e][perm(t)] — transposed; t permuted within 8-groups
        const int pg = perm8(g);
        #pragma unroll
        for (int mf = 0; mf < 4; mf++)
            #pragma unroll
            for (int nf = 0; nf < 4; nf++) {
                const int e0 = eb + nf * 8 + 2 * tig;
                const int m = m0 + wm + mf * 16 + g;
                const int b = m >> 11, t = m & 2047;
                const int tb = t & ~7;
                const size_t base = (size_t)(b * H_ + hh) * E_;
                Out[(base + e0)     * T_ + tb + pg]     = to_tf32(c[mf][nf][0]);
                Out[(base + e0 + 1) * T_ + tb + pg]     = to_tf32(c[mf][nf][1]);
                Out[(base + e0)     * T_ + tb + 8 + pg] = to_tf32(c[mf][nf][2]);
                Out[(base + e0 + 1) * T_ + tb + 8 + pg] = to_tf32(c[mf][nf][3]);
            }
    }
}

// ---------------------------------------------------------------------------
// Kernel 2: tf32 mma flash attention, v9: paired (float2) K and V fragment
// loads via gmem permutation. Otherwise identical to proven attn9.
// ---------------------------------------------------------------------------
#define SK 72
#define SV 72
#define SP 68
#define KBUF_W (64 * SK)    // 4608 words
#define VBUF_W (64 * SV)    // 4608 words
#define P_W    (128 * SP)   // 8704 words
#define ATTN_SMEM_BYTES ((2 * KBUF_W + 2 * VBUF_W + P_W) * 4)   // 108544

__global__ __launch_bounds__(128, 2) void attn11_kernel()
{
    extern __shared__ float smf[];
    float* Kb = smf;                          // 2 x KBUF_W (rows=key, cols=perm(e))
    float* Vb = smf + 2 * KBUF_W;             // 2 x VBUF_W (rows=e, cols=perm(key))
    float* Ps = smf + 2 * KBUF_W + 2 * VBUF_W;

    const int tid  = threadIdx.x;
    const int warp = tid >> 5, lane = tid & 31;
    const int g = lane >> 2, tig = lane & 3;
    const int bh = blockIdx.y;
    const int q0 = blockIdx.x * 128;
    const int wrow = warp * 32;

    const float* Qg = g_q + (size_t)bh * T_ * E_;
    const float* Kg = g_k + (size_t)bh * T_ * E_;
    const float* Vg = g_v + (size_t)bh * E_ * T_;   // transposed layout

    const uint32_t sb    = smem_u32(smf);
    const uint32_t kbase = sb;
    const uint32_t vbase = sb + 2 * KBUF_W * 4;

    auto prefetch = [&](int tile) {
        const int s = tile & 1;
        const size_t t0 = (size_t)tile * 64;
        #pragma unroll
        for (int i = 0; i < 8; i++) {
            const int idx = i * 128 + tid;
            const int r = idx >> 4, c4 = (idx & 15) * 4;
            // K: rows = 64 keys of this tile, cols = 64 permuted e
            cpa16(kbase + (uint32_t)(s * KBUF_W + r * SK + c4) * 4,
                  Kg + (t0 + r) * 64 + c4);
            // V: rows = 64 e, cols = this tile's 64 permuted keys
            cpa16(vbase + (uint32_t)(s * VBUF_W + r * SV + c4) * 4,
                  Vg + (size_t)r * T_ + t0 + c4);
        }
        CP_COMMIT();
    };

    prefetch(0);

    uint32_t qf[8][2][4];
    #pragma unroll
    for (int kf = 0; kf < 8; kf++)
        #pragma unroll
        for (int mf = 0; mf < 2; mf++) {
            const int r = q0 + wrow + mf * 16;
            qf[kf][mf][0] = __float_as_uint(Qg[(size_t)(r + g)     * 64 + kf * 8 + tig]);
            qf[kf][mf][1] = __float_as_uint(Qg[(size_t)(r + 8 + g) * 64 + kf * 8 + tig]);
            qf[kf][mf][2] = __float_as_uint(Qg[(size_t)(r + g)     * 64 + kf * 8 + tig + 4]);
            qf[kf][mf][3] = __float_as_uint(Qg[(size_t)(r + 8 + g) * 64 + kf * 8 + tig + 4]);
        }

    float o[2][8][4];
    #pragma unroll
    for (int mf = 0; mf < 2; mf++)
        #pragma unroll
        for (int nf = 0; nf < 8; nf++)
            #pragma unroll
            for (int j = 0; j < 4; j++) o[mf][nf][j] = 0.0f;
    float li[4] = {0.0f, 0.0f, 0.0f, 0.0f};

    for (int t = 0; t < 32; t++) {
        CP_WAIT0();
        __syncthreads();
        if (t < 31) prefetch(t + 1);

        const float* Kt = Kb + (t & 1) * KBUF_W;
        const float* Vt = Vb + (t & 1) * VBUF_W;

        #pragma unroll
        for (int nh = 0; nh < 2; nh++) {
            float c[2][4][4];
            #pragma unroll
            for (int mf = 0; mf < 2; mf++)
                #pragma unroll
                for (int nf = 0; nf < 4; nf++)
                    #pragma unroll
                    for (int j = 0; j < 4; j++) c[mf][nf][j] = 0.0f;
            #pragma unroll
            for (int kf = 0; kf < 8; kf++) {
                #pragma unroll
                for (int nf = 0; nf < 4; nf++) {
                    // paired load: (e kf*8+tig, e kf*8+tig+4) adjacent via perm
                    const float2 kb2 = *(const float2*)
                        &Kt[(nh * 32 + nf * 8 + g) * SK + kf * 8 + 2 * tig];
                    const uint32_t b0 = __float_as_uint(kb2.x);
                    const uint32_t b1 = __float_as_uint(kb2.y);
                    mma_tf32(c[0][nf], qf[kf][0], b0, b1);
                    mma_tf32(c[1][nf], qf[kf][1], b0, b1);
                }
            }
            #pragma unroll
            for (int mf = 0; mf < 2; mf++)
                #pragma unroll
                for (int nf = 0; nf < 4; nf++) {
                    const float p0 = fast_ex2(c[mf][nf][0] * LOG2E_F);
                    const float p1 = fast_ex2(c[mf][nf][1] * LOG2E_F);
                    const float p2 = fast_ex2(c[mf][nf][2] * LOG2E_F);
                    const float p3 = fast_ex2(c[mf][nf][3] * LOG2E_F);
                    li[mf * 2 + 0] += p0 + p1;
                    li[mf * 2 + 1] += p2 + p3;
                    const int col = nh * 32 + nf * 8 + 2 * tig;
                    const int r0 = wrow + mf * 16 + g;
                    *(float2*)&Ps[r0 * SP + col]       = make_float2(p0, p1);
                    *(float2*)&Ps[(r0 + 8) * SP + col] = make_float2(p2, p3);
                }
        }
        __syncwarp();

        #pragma unroll
        for (int kf = 0; kf < 8; kf++) {
            uint32_t a[2][4];
            #pragma unroll
            for (int mf = 0; mf < 2; mf++) {
                const float* pb = &Ps[(wrow + mf * 16) * SP + kf * 8];
                a[mf][0] = __float_as_uint(pb[g * SP + tig]);
                a[mf][1] = __float_as_uint(pb[(g + 8) * SP + tig]);
                a[mf][2] = __float_as_uint(pb[g * SP + tig + 4]);
                a[mf][3] = __float_as_uint(pb[(g + 8) * SP + tig + 4]);
            }
            #pragma unroll
            for (int nf = 0; nf < 8; nf++) {
                // paired load: (key kf*8+tig, key kf*8+tig+4) adjacent via perm
                const float2 vv = *(const float2*)
                    &Vt[(nf * 8 + g) * SV + kf * 8 + 2 * tig];
                const uint32_t b0 = __float_as_uint(vv.x);
                const uint32_t b1 = __float_as_uint(vv.y);
                mma_tf32(o[0][nf], a[0], b0, b1);
                mma_tf32(o[1][nf], a[1], b0, b1);
            }
        }
    }

    #pragma unroll
    for (int i = 0; i < 4; i++) {
        li[i] += __shfl_xor_sync(0xffffffff, li[i], 1);
        li[i] += __shfl_xor_sync(0xffffffff, li[i], 2);
    }
    const float inv0 = 1.0f / li[0], inv1 = 1.0f / li[1];
    const float inv2 = 1.0f / li[2], inv3 = 1.0f / li[3];

    float* Og = g_o + ((size_t)bh * T_ + q0) * 64;
    #pragma unroll
    for (int mf = 0; mf < 2; mf++) {
        const float ia = (mf == 0) ? inv0 : inv2;
        const float ib = (mf == 0) ? inv1 : inv3;
        #pragma unroll
        for (int nf = 0; nf < 8; nf++) {
            const int col = nf * 8 + 2 * tig;
            const int r0 = wrow + mf * 16 + g;
            *(float2*)&Og[(size_t)r0 * 64 + col] =
                make_float2(o[mf][nf][0] * ia, o[mf][nf][1] * ia);
            *(float2*)&Og[(size_t)(r0 + 8) * 64 + col] =
                make_float2(o[mf][nf][2] * ib, o[mf][nf][3] * ib);
        }
    }
}

// ---------------------------------------------------------------------------
// Kernel 3: head merge (unchanged)
// ---------------------------------------------------------------------------
__global__ __launch_bounds__(256) void merge_kernel(
    const float* __restrict__ mw, float* __restrict__ out)
{
    __shared__ float w[H_][E_];
    const int tid = threadIdx.x;
    if (tid < E_) {
        float vals[H_];
        float mx = -CUDART_INF_F;
        #pragma unroll
        for (int h = 0; h < H_; h++) {
            vals[h] = mw[h * E_ + tid];
            mx = fmaxf(mx, vals[h]);
        }
        float sum = 0.0f;
        #pragma unroll
        for (int h = 0; h < H_; h++) {
            vals[h] = __expf(vals[h] - mx);
            sum += vals[h];
        }
        const float inv = 1.0f / sum;
        #pragma unroll
        for (int h = 0; h < H_; h++) w[h][tid] = vals[h] * inv;
    }
    __syncthreads();

    const int i = blockIdx.x * 256 + tid;
    const int e  = i & 63;
    const int bt = i >> 6;
    const int b  = bt >> 11;
    const int t  = bt & 2047;
    float acc = 0.0f;
    #pragma unroll
    for (int h = 0; h < H_; h++)
        acc = fmaf(w[h][e], g_o[(((size_t)(b * H_ + h) * T_ + t) << 6) + e], acc);
    out[i] = acc;
}

// ---------------------------------------------------------------------------
extern "C" void kernel_launch(void* const* d_in, const int* in_sizes, int n_in,
                              void* d_out, int out_size)
{
    const float* observe = (const float*)d_in[0];
    const float* state   = (const float*)d_in[1];
    const float* Wq      = (const float*)d_in[2];
    const float* Wk      = (const float*)d_in[3];
    const float* Wv      = (const float*)d_in[4];
    const float* merge_w = (const float*)d_in[5];
    float* out = (float*)d_out;

    cudaFuncSetAttribute(proj4_kernel, cudaFuncAttributeMaxDynamicSharedMemorySize,
                         PROJ_SMEM_BYTES);
    cudaFuncSetAttribute(attn11_kernel, cudaFuncAttributeMaxDynamicSharedMemorySize,
                         ATTN_SMEM_BYTES);

    // 0) Pre-convert operands to split-bf16
    convx_kernel<<<8192, 256>>>(observe, state);
    {
        dim3 grid(2, 256, 3);
        convw_kernel<<<grid, 256>>>(Wq, Wk, Wv);
    }
    // 1) QKV projections (K e-permuted, V transposed + key-permuted)
    {
        dim3 grid(NQK_ / 128, (B_ * T_) / 128, 3);
        proj4_kernel<<<grid, 256, PROJ_SMEM_BYTES>>>();
    }
    // 2) tf32 mma attention with paired fragment loads
    {
        dim3 grid(T_ / 128, BH_);
        attn11_kernel<<<grid, 128, ATTN_SMEM_BYTES>>>();
    }
    // 3) Merge
    {
        const int total = B_ * T_ * E_;
        merge_kernel<<<total / 256, 256>>>(merge_w, out);
    }
}

// round 17
// speedup vs baseline: 1.7816x; 1.7816x over previous
#include <cuda_runtime.h>
#include <cuda_bf16.h>
#include <math_constants.h>
#include <cstdint>

// Problem constants
#define B_   4
#define T_   2048
#define OBS_ 512
#define ST_  512
#define H_   8
#define E_   64
#define BH_  (B_ * H_)          // 32
#define NQK_ (H_ * E_)          // 512

#define LOG2E_F 1.4426950408889634f

// Scratch (fp32, tf32-rounded):
//   g_q: [bh][t][e]
//   g_k: [bh][t][perm(e)]  e permuted within 8-groups: c -> c<4 ? 2c : 2(c-4)+1
//   g_v: [bh][t][e]        (row-major, unchanged)
//   g_o: [bh][t][e]
__device__ float g_q[BH_ * T_ * E_];
__device__ float g_k[BH_ * T_ * E_];
__device__ float g_v[BH_ * T_ * E_];
__device__ float g_o[BH_ * T_ * E_];

// Pre-converted bf16 hi/lo operands (packed bf16x2 words, [row][kpair])
__device__ uint32_t g_xh[16384 * 256];   // rows 0..8191 = obs, 8192..16383 = state
__device__ uint32_t g_xl[16384 * 256];
__device__ uint32_t g_wh[3 * 512 * 256]; // [z][n][kpair]
__device__ uint32_t g_wl[3 * 512 * 256];

__device__ __forceinline__ uint32_t smem_u32(const void* p) {
    uint32_t a;
    asm("{ .reg .u64 t; cvta.to.shared.u64 t, %1; cvt.u32.u64 %0, t; }" : "=r"(a) : "l"(p));
    return a;
}
__device__ __forceinline__ float to_tf32(float x) {
    float y; asm("cvt.rna.tf32.f32 %0, %1;" : "=f"(y) : "f"(x)); return y;
}
__device__ __forceinline__ float fast_ex2(float x) {
    float y; asm("ex2.approx.f32 %0, %1;" : "=f"(y) : "f"(x)); return y;
}
// m16n8k8 tf32 mma (A row-major, B col-major), D = A*B + D
__device__ __forceinline__ void mma_tf32(float* c, const uint32_t* a,
                                         uint32_t b0, uint32_t b1) {
    asm volatile(
        "mma.sync.aligned.m16n8k8.row.col.f32.tf32.tf32.f32 "
        "{%0,%1,%2,%3}, {%4,%5,%6,%7}, {%8,%9}, {%0,%1,%2,%3};"
        : "+f"(c[0]), "+f"(c[1]), "+f"(c[2]), "+f"(c[3])
        : "r"(a[0]), "r"(a[1]), "r"(a[2]), "r"(a[3]), "r"(b0), "r"(b1));
}
// m16n8k16 bf16 mma (A row-major, B col-major), D = A*B + D
__device__ __forceinline__ void mma_bf16(float* c, const uint32_t* a,
                                         uint32_t b0, uint32_t b1) {
    asm volatile(
        "mma.sync.aligned.m16n8k16.row.col.f32.bf16.bf16.f32 "
        "{%0,%1,%2,%3}, {%4,%5,%6,%7}, {%8,%9}, {%0,%1,%2,%3};"
        : "+f"(c[0]), "+f"(c[1]), "+f"(c[2]), "+f"(c[3])
        : "r"(a[0]), "r"(a[1]), "r"(a[2]), "r"(a[3]), "r"(b0), "r"(b1));
}
__device__ __forceinline__ uint32_t pack_bf16(float lo, float hi) {
    uint32_t r;
    asm("cvt.rn.bf16x2.f32 %0, %1, %2;" : "=r"(r) : "f"(hi), "f"(lo));
    return r;
}
__device__ __forceinline__ float unpk_lo(uint32_t p) { return __uint_as_float(p << 16); }
__device__ __forceinline__ float unpk_hi(uint32_t p) { return __uint_as_float(p & 0xFFFF0000u); }

__device__ __forceinline__ void cpa16(uint32_t dst, const void* src) {
    asm volatile("cp.async.cg.shared.global [%0], [%1], 16;" :: "r"(dst), "l"(src));
}
#define CP_COMMIT() asm volatile("cp.async.commit_group;" ::: "memory")
#define CP_WAIT1()  asm volatile("cp.async.wait_group 1;" ::: "memory")
#define CP_WAIT0()  asm volatile("cp.async.wait_group 0;" ::: "memory")

// perm within an 8-group: c -> c<4 ? 2c : 2(c-4)+1 (pairs (c, c+4) adjacent)
__device__ __forceinline__ int perm8(int c) { return (c < 4) ? (2 * c) : (2 * (c - 4) + 1); }

// ---------------------------------------------------------------------------
// Kernel 0a: convert X (obs ++ state) to packed bf16 hi/lo [row][kpair]
// ---------------------------------------------------------------------------
__global__ __launch_bounds__(256) void convx_kernel(
    const float* __restrict__ obs, const float* __restrict__ st)
{
    const int idx = blockIdx.x * 256 + threadIdx.x;
    const int row = idx >> 7;
    const int c4  = (idx & 127) * 4;
    const float* src = (row < 8192) ? obs + (size_t)row * 512 + c4
                                    : st + (size_t)(row - 8192) * 512 + c4;
    const float4 x = *(const float4*)src;
    const uint32_t h0 = pack_bf16(x.x, x.y);
    const uint32_t h1 = pack_bf16(x.z, x.w);
    const uint32_t l0 = pack_bf16(x.x - unpk_lo(h0), x.y - unpk_hi(h0));
    const uint32_t l1 = pack_bf16(x.z - unpk_lo(h1), x.w - unpk_hi(h1));
    const size_t o = (size_t)row * 256 + (c4 >> 1);
    *(uint2*)&g_xh[o] = make_uint2(h0, h1);
    *(uint2*)&g_xl[o] = make_uint2(l0, l1);
}

// ---------------------------------------------------------------------------
// Kernel 0b: convert W (Wq/Wk/Wv) to transposed packed bf16 hi/lo [z][n][kpair]
// ---------------------------------------------------------------------------
__global__ __launch_bounds__(256) void convw_kernel(
    const float* __restrict__ Wq, const float* __restrict__ Wk,
    const float* __restrict__ Wv)
{
    const int z = blockIdx.z;
    const float* W = (z == 0) ? Wq : ((z == 1) ? Wk : Wv);
    const int n  = blockIdx.x * 256 + threadIdx.x;
    const int kp = blockIdx.y;
    const float x0 = W[(size_t)(2 * kp + 0) * 512 + n];
    const float x1 = W[(size_t)(2 * kp + 1) * 512 + n];
    const uint32_t h = pack_bf16(x0, x1);
    const uint32_t l = pack_bf16(x0 - unpk_lo(h), x1 - unpk_hi(h));
    const size_t o = ((size_t)z * 512 + n) * 256 + kp;
    g_wh[o] = h;
    g_wl[o] = l;
}

// ---------------------------------------------------------------------------
// Kernel 1: QKV projection (R14 proj3) with K epilogue column permutation.
// ---------------------------------------------------------------------------
#define SA 24
#define SB 20
#define STG_A (128 * SA)
#define STG_B (128 * SB)
#define PROJ_SMEM_BYTES ((4 * STG_A + 4 * STG_B) * 4)   // 90112

__global__ __launch_bounds__(256, 2) void proj5_kernel()
{
    extern __shared__ uint32_t sm[];
    const uint32_t sb = smem_u32(sm);

    const int z = blockIdx.z;
    float* Out = (z == 0) ? g_q : ((z == 1) ? g_k : g_v);
    const float scale = (z == 0) ? 0.125f : 1.0f;
    const int row_base = (z == 0) ? 0 : 8192;

    const int m0 = blockIdx.y * 128;
    const int n0 = blockIdx.x * 128;

    const int tid  = threadIdx.x;
    const int warp = tid >> 5, lane = tid & 31;
    const int g = lane >> 2, tig = lane & 3;
    const int wm = (warp >> 2) * 64;
    const int wn = (warp & 3) * 32;

    const uint32_t* Xh = g_xh + (size_t)(row_base + m0) * 256;
    const uint32_t* Xl = g_xl + (size_t)(row_base + m0) * 256;
    const uint32_t* Wh = g_wh + ((size_t)z * 512 + n0) * 256;
    const uint32_t* Wl = g_wl + ((size_t)z * 512 + n0) * 256;

    auto load_stage = [&](int s, int k0) {
        const int kw = k0 >> 1;
        const uint32_t ah = sb + (uint32_t)(s * STG_A) * 4;
        const uint32_t al = sb + (uint32_t)((2 + s) * STG_A) * 4;
        const uint32_t bhh = sb + (uint32_t)(4 * STG_A + s * STG_B) * 4;
        const uint32_t bll = sb + (uint32_t)(4 * STG_A + (2 + s) * STG_B) * 4;
        #pragma unroll
        for (int it = 0; it < 2; it++) {
            const int u = it * 256 + tid;
            const int r = u >> 2, ch = (u & 3) * 4;
            cpa16(ah + (uint32_t)(r * SA + ch) * 4, Xh + (size_t)r * 256 + kw + ch);
            cpa16(al + (uint32_t)(r * SA + ch) * 4, Xl + (size_t)r * 256 + kw + ch);
            cpa16(bhh + (uint32_t)(r * SB + ch) * 4, Wh + (size_t)r * 256 + kw + ch);
            cpa16(bll + (uint32_t)(r * SB + ch) * 4, Wl + (size_t)r * 256 + kw + ch);
        }
    };

    float c[4][4][4];
    #pragma unroll
    for (int mf = 0; mf < 4; mf++)
        #pragma unroll
        for (int nf = 0; nf < 4; nf++)
            #pragma unroll
            for (int j = 0; j < 4; j++) c[mf][nf][j] = 0.0f;

    load_stage(0, 0);
    CP_COMMIT();

    for (int kt = 0; kt < 16; kt++) {
        if (kt < 15) {
            load_stage((kt + 1) & 1, (kt + 1) * 32);
            CP_COMMIT();
            CP_WAIT1();
        } else {
            CP_WAIT0();
        }
        __syncthreads();

        const int s = kt & 1;
        const uint32_t* Ash = sm + s * STG_A;
        const uint32_t* Asl = sm + (2 + s) * STG_A;
        const uint32_t* Bsh = sm + 4 * STG_A + s * STG_B;
        const uint32_t* Bsl = sm + 4 * STG_A + (2 + s) * STG_B;

        #pragma unroll
        for (int ks = 0; ks < 2; ks++) {
            const int kw = ks * 8 + 2 * tig;
            uint32_t ah[4][4];
            #pragma unroll
            for (int mf = 0; mf < 4; mf++) {
                const int r0 = wm + mf * 16 + g;
                const uint2 p = *(const uint2*)&Ash[r0 * SA + kw];
                const uint2 q = *(const uint2*)&Ash[(r0 + 8) * SA + kw];
                ah[mf][0] = p.x; ah[mf][1] = q.x; ah[mf][2] = p.y; ah[mf][3] = q.y;
            }
            uint2 bh[4];
            #pragma unroll
            for (int nf = 0; nf < 4; nf++) {
                const int nr = wn + nf * 8 + g;
                bh[nf] = *(const uint2*)&Bsh[nr * SB + kw];
                const uint2 bl = *(const uint2*)&Bsl[nr * SB + kw];
                #pragma unroll
                for (int mf = 0; mf < 4; mf++) {
                    mma_bf16(c[mf][nf], ah[mf], bh[nf].x, bh[nf].y);
                    mma_bf16(c[mf][nf], ah[mf], bl.x, bl.y);
                }
            }
            #pragma unroll
            for (int mf = 0; mf < 4; mf++) {
                const int r0 = wm + mf * 16 + g;
                const uint2 pl = *(const uint2*)&Asl[r0 * SA + kw];
                const uint2 ql = *(const uint2*)&Asl[(r0 + 8) * SA + kw];
                uint32_t al_[4] = { pl.x, ql.x, pl.y, ql.y };
                #pragma unroll
                for (int nf = 0; nf < 4; nf++)
                    mma_bf16(c[mf][nf], al_, bh[nf].x, bh[nf].y);
            }
        }
        __syncthreads();
    }

    // Epilogue: [bh][t][e], tf32-rounded. K (z==1) gets column permutation.
    const int hh = (n0 + wn) >> 6;
    const int eb = wn & 63;
    if (z != 1) {
        #pragma unroll
        for (int mf = 0; mf < 4; mf++)
            #pragma unroll
            for (int nf = 0; nf < 4; nf++) {
                const int e = eb + nf * 8 + 2 * tig;
                const int m = m0 + wm + mf * 16 + g;
                const int b = m >> 11, t = m & 2047;
                float* p0 = &Out[(((size_t)(b * H_ + hh) * T_ + t) << 6) + e];
                p0[0] = to_tf32(c[mf][nf][0] * scale);
                p0[1] = to_tf32(c[mf][nf][1] * scale);
                float* p1 = &Out[(((size_t)(b * H_ + hh) * T_ + (t + 8)) << 6) + e];
                p1[0] = to_tf32(c[mf][nf][2] * scale);
                p1[1] = to_tf32(c[mf][nf][3] * scale);
            }
    } else {
        // K: columns permuted within each 8-group; stores stay inside the
        // same 32B segments -> sector count unchanged.
        const int p0i = perm8(2 * tig);
        const int p1i = perm8(2 * tig + 1);
        #pragma unroll
        for (int mf = 0; mf < 4; mf++)
            #pragma unroll
            for (int nf = 0; nf < 4; nf++) {
                const int ebase = eb + nf * 8;
                const int m = m0 + wm + mf * 16 + g;
                const int b = m >> 11, t = m & 2047;
                float* r0 = &Out[(((size_t)(b * H_ + hh) * T_ + t) << 6) + ebase];
                r0[p0i] = to_tf32(c[mf][nf][0]);
                r0[p1i] = to_tf32(c[mf][nf][1]);
                float* r1 = &Out[(((size_t)(b * H_ + hh) * T_ + (t + 8)) << 6) + ebase];
                r1[p0i] = to_tf32(c[mf][nf][2]);
                r1[p1i] = to_tf32(c[mf][nf][3]);
            }
    }
}

// ---------------------------------------------------------------------------
// Kernel 2: tf32 mma flash attention (R11/R14 attn9) with paired K loads.
// V path untouched (row-major, scalar LDS). Bit-identical arithmetic.
// ---------------------------------------------------------------------------
#define SK 72
#define SV 72
#define SP 68
#define KBUF_W (64 * SK)    // 4608 words
#define VBUF_W (64 * SV)    // 4608 words
#define P_W    (128 * SP)   // 8704 words
#define ATTN_SMEM_BYTES ((2 * KBUF_W + 2 * VBUF_W + P_W) * 4)   // 108544

__global__ __launch_bounds__(128, 2) void attn12_kernel()
{
    extern __shared__ float smf[];
    float* Kb = smf;                          // 2 x KBUF_W (rows=key, cols=perm(e))
    float* Vb = smf + 2 * KBUF_W;             // 2 x VBUF_W (rows=key, cols=e)
    float* Ps = smf + 2 * KBUF_W + 2 * VBUF_W;

    const int tid  = threadIdx.x;
    const int warp = tid >> 5, lane = tid & 31;
    const int g = lane >> 2, tig = lane & 3;
    const int bh = blockIdx.y;
    const int q0 = blockIdx.x * 128;
    const int wrow = warp * 32;

    const float* Qg = g_q + (size_t)bh * T_ * E_;
    const float* Kg = g_k + (size_t)bh * T_ * E_;
    const float* Vg = g_v + (size_t)bh * T_ * E_;

    const uint32_t sb    = smem_u32(smf);
    const uint32_t kbase = sb;
    const uint32_t vbase = sb + 2 * KBUF_W * 4;

    auto prefetch = [&](int tile) {
        const int s = tile & 1;
        const size_t r0 = (size_t)tile * 64;
        #pragma unroll
        for (int i = 0; i < 8; i++) {
            const int idx = i * 128 + tid;
            const int r = idx >> 4, c4 = (idx & 15) * 4;
            cpa16(kbase + (uint32_t)(s * KBUF_W + r * SK + c4) * 4,
                  Kg + (r0 + r) * 64 + c4);
            cpa16(vbase + (uint32_t)(s * VBUF_W + r * SV + c4) * 4,
                  Vg + (r0 + r) * 64 + c4);
        }
        CP_COMMIT();
    };

    prefetch(0);

    uint32_t qf[8][2][4];
    #pragma unroll
    for (int kf = 0; kf < 8; kf++)
        #pragma unroll
        for (int mf = 0; mf < 2; mf++) {
            const int r = q0 + wrow + mf * 16;
            qf[kf][mf][0] = __float_as_uint(Qg[(size_t)(r + g)     * 64 + kf * 8 + tig]);
            qf[kf][mf][1] = __float_as_uint(Qg[(size_t)(r + 8 + g) * 64 + kf * 8 + tig]);
            qf[kf][mf][2] = __float_as_uint(Qg[(size_t)(r + g)     * 64 + kf * 8 + tig + 4]);
            qf[kf][mf][3] = __float_as_uint(Qg[(size_t)(r + 8 + g) * 64 + kf * 8 + tig + 4]);
        }

    float o[2][8][4];
    #pragma unroll
    for (int mf = 0; mf < 2; mf++)
        #pragma unroll
        for (int nf = 0; nf < 8; nf++)
            #pragma unroll
            for (int j = 0; j < 4; j++) o[mf][nf][j] = 0.0f;
    float li[4] = {0.0f, 0.0f, 0.0f, 0.0f};

    for (int t = 0; t < 32; t++) {
        CP_WAIT0();
        __syncthreads();
        if (t < 31) prefetch(t + 1);

        const float* Kt = Kb + (t & 1) * KBUF_W;
        const float* Vt = Vb + (t & 1) * VBUF_W;

        #pragma unroll
        for (int nh = 0; nh < 2; nh++) {
            float c[2][4][4];
            #pragma unroll
            for (int mf = 0; mf < 2; mf++)
                #pragma unroll
                for (int nf = 0; nf < 4; nf++)
                    #pragma unroll
                    for (int j = 0; j < 4; j++) c[mf][nf][j] = 0.0f;
            #pragma unroll
            for (int kf = 0; kf < 8; kf++) {
                #pragma unroll
                for (int nf = 0; nf < 4; nf++) {
                    // paired: positions (2tig, 2tig+1) hold original e (tig, tig+4)
                    const float2 kb2 = *(const float2*)
                        &Kt[(nh * 32 + nf * 8 + g) * SK + kf * 8 + 2 * tig];
                    const uint32_t b0 = __float_as_uint(kb2.x);
                    const uint32_t b1 = __float_as_uint(kb2.y);
                    mma_tf32(c[0][nf], qf[kf][0], b0, b1);
                    mma_tf32(c[1][nf], qf[kf][1], b0, b1);
                }
            }
            #pragma unroll
            for (int mf = 0; mf < 2; mf++)
                #pragma unroll
                for (int nf = 0; nf < 4; nf++) {
                    const float p0 = fast_ex2(c[mf][nf][0] * LOG2E_F);
                    const float p1 = fast_ex2(c[mf][nf][1] * LOG2E_F);
                    const float p2 = fast_ex2(c[mf][nf][2] * LOG2E_F);
                    const float p3 = fast_ex2(c[mf][nf][3] * LOG2E_F);
                    li[mf * 2 + 0] += p0 + p1;
                    li[mf * 2 + 1] += p2 + p3;
                    const int col = nh * 32 + nf * 8 + 2 * tig;
                    const int r0 = wrow + mf * 16 + g;
                    *(float2*)&Ps[r0 * SP + col]       = make_float2(p0, p1);
                    *(float2*)&Ps[(r0 + 8) * SP + col] = make_float2(p2, p3);
                }
        }
        __syncwarp();

        #pragma unroll
        for (int kf = 0; kf < 8; kf++) {
            uint32_t a[2][4];
            #pragma unroll
            for (int mf = 0; mf < 2; mf++) {
                const float* pb = &Ps[(wrow + mf * 16) * SP + kf * 8];
                a[mf][0] = __float_as_uint(pb[g * SP + tig]);
                a[mf][1] = __float_as_uint(pb[(g + 8) * SP + tig]);
                a[mf][2] = __float_as_uint(pb[g * SP + tig + 4]);
                a[mf][3] = __float_as_uint(pb[(g + 8) * SP + tig + 4]);
            }
            const float* vr = &Vt[(kf * 8 + tig) * SV + g];
            #pragma unroll
            for (int nf = 0; nf < 8; nf++) {
                const uint32_t b0 = __float_as_uint(vr[nf * 8]);
                const uint32_t b1 = __float_as_uint(vr[4 * SV + nf * 8]);
                mma_tf32(o[0][nf], a[0], b0, b1);
                mma_tf32(o[1][nf], a[1], b0, b1);
            }
        }
    }

    #pragma unroll
    for (int i = 0; i < 4; i++) {
        li[i] += __shfl_xor_sync(0xffffffff, li[i], 1);
        li[i] += __shfl_xor_sync(0xffffffff, li[i], 2);
    }
    const float inv0 = 1.0f / li[0], inv1 = 1.0f / li[1];
    const float inv2 = 1.0f / li[2], inv3 = 1.0f / li[3];

    float* Og = g_o + ((size_t)bh * T_ + q0) * 64;
    #pragma unroll
    for (int mf = 0; mf < 2; mf++) {
        const float ia = (mf == 0) ? inv0 : inv2;
        const float ib = (mf == 0) ? inv1 : inv3;
        #pragma unroll
        for (int nf = 0; nf < 8; nf++) {
            const int col = nf * 8 + 2 * tig;
            const int r0 = wrow + mf * 16 + g;
            *(float2*)&Og[(size_t)r0 * 64 + col] =
                make_float2(o[mf][nf][0] * ia, o[mf][nf][1] * ia);
            *(float2*)&Og[(size_t)(r0 + 8) * 64 + col] =
                make_float2(o[mf][nf][2] * ib, o[mf][nf][3] * ib);
        }
    }
}

// ---------------------------------------------------------------------------
// Kernel 3: head merge (unchanged)
// ---------------------------------------------------------------------------
__global__ __launch_bounds__(256) void merge_kernel(
    const float* __restrict__ mw, float* __restrict__ out)
{
    __shared__ float w[H_][E_];
    const int tid = threadIdx.x;
    if (tid < E_) {
        float vals[H_];
        float mx = -CUDART_INF_F;
        #pragma unroll
        for (int h = 0; h < H_; h++) {
            vals[h] = mw[h * E_ + tid];
            mx = fmaxf(mx, vals[h]);
        }
        float sum = 0.0f;
        #pragma unroll
        for (int h = 0; h < H_; h++) {
            vals[h] = __expf(vals[h] - mx);
            sum += vals[h];
        }
        const float inv = 1.0f / sum;
        #pragma unroll
        for (int h = 0; h < H_; h++) w[h][tid] = vals[h] * inv;
    }
    __syncthreads();

    const int i = blockIdx.x * 256 + tid;
    const int e  = i & 63;
    const int bt = i >> 6;
    const int b  = bt >> 11;
    const int t  = bt & 2047;
    float acc = 0.0f;
    #pragma unroll
    for (int h = 0; h < H_; h++)
        acc = fmaf(w[h][e], g_o[(((size_t)(b * H_ + h) * T_ + t) << 6) + e], acc);
    out[i] = acc;
}

// ---------------------------------------------------------------------------
extern "C" void kernel_launch(void* const* d_in, const int* in_sizes, int n_in,
                              void* d_out, int out_size)
{
    const float* observe = (const float*)d_in[0];
    const float* state   = (const float*)d_in[1];
    const float* Wq      = (const float*)d_in[2];
    const float* Wk      = (const float*)d_in[3];
    const float* Wv      = (const float*)d_in[4];
    const float* merge_w = (const float*)d_in[5];
    float* out = (float*)d_out;

    cudaFuncSetAttribute(proj5_kernel, cudaFuncAttributeMaxDynamicSharedMemorySize,
                         PROJ_SMEM_BYTES);
    cudaFuncSetAttribute(attn12_kernel, cudaFuncAttributeMaxDynamicSharedMemorySize,
                         ATTN_SMEM_BYTES);

    // 0) Pre-convert operands to split-bf16
    convx_kernel<<<8192, 256>>>(observe, state);
    {
        dim3 grid(2, 256, 3);
        convw_kernel<<<grid, 256>>>(Wq, Wk, Wv);
    }
    // 1) QKV projections (K columns permuted within 8-groups)
    {
        dim3 grid(NQK_ / 128, (B_ * T_) / 128, 3);
        proj5_kernel<<<grid, 256, PROJ_SMEM_BYTES>>>();
    }
    // 2) tf32 mma attention with paired K fragment loads
    {
        dim3 grid(T_ / 128, BH_);
        attn12_kernel<<<grid, 128, ATTN_SMEM_BYTES>>>();
    }
    // 3) Merge
    {
        const int total = B_ * T_ * E_;
        merge_kernel<<<total / 256, 256>>>(merge_w, out);
    }
}